// round 6
// baseline (speedup 1.0000x reference)
#include <cuda_runtime.h>

// TransducerJoint: h[b,t,u,:] = f[b,t,:] + g[b,u,:] if t < f_len[b] && u < g_len[b] else 0
// B=16, T=256, U=96, H=512 (fp32). Output 805 MB -> pure HBM-write-bound.
// R6: one CTA per (b,t) row -> 192KB contiguous write span per CTA for maximal
//     DRAM page locality. 256 threads = 2 u-lanes x 128 h4-lanes, 48 u-pair
//     iterations unrolled x6. Hoisted n_valid; float4 __stcs stores.

#define B_ 16
#define T_ 256
#define U_ 96
#define H_ 512
#define H4_ (H_ / 4)      // 128 float4 per H-row

__global__ __launch_bounds__(256) void transducer_joint_kernel(
    const float4* __restrict__ f,      // (B, T, H/4)
    const float4* __restrict__ g,      // (B, U, H/4)
    const int*    __restrict__ f_len,  // (B,)
    const int*    __restrict__ g_len,  // (B,)
    float4*       __restrict__ out)    // (B, T, U, H/4)
{
    const int h4    = threadIdx.x & 127;   // 0..127
    const int ulane = threadIdx.x >> 7;    // 0..1
    const int t     = blockIdx.x;
    const int b     = blockIdx.y;

    // valid u count for this (b,t), computed once per CTA
    const int n_valid = (t < f_len[b]) ? g_len[b] : 0;

    // f slice for this thread: loaded once, reused for all 48 u's
    const float4 f4 = __ldg(f + ((size_t)b * T_ + t) * H4_ + h4);

    const float4* gbase = g + ((size_t)b * U_) * H4_ + h4;
    float4* obase = out + (((size_t)b * T_ + t) * U_) * H4_ + h4;

    const float4 zero = make_float4(0.f, 0.f, 0.f, 0.f);

    // each thread covers u = ulane, ulane+2, ..., ulane+94  (48 iterations)
#pragma unroll 6
    for (int i = 0; i < U_ / 2; ++i) {
        const int u = ulane + 2 * i;
        float4 r = zero;
        if (u < n_valid) {
            const float4 g4 = __ldg(gbase + (size_t)u * H4_);
            r.x = f4.x + g4.x;
            r.y = f4.y + g4.y;
            r.z = f4.z + g4.z;
            r.w = f4.w + g4.w;
        }
        __stcs(obase + (size_t)u * H4_, r);
    }
}

extern "C" void kernel_launch(void* const* d_in, const int* in_sizes, int n_in,
                              void* d_out, int out_size)
{
    const float4* f     = (const float4*)d_in[0];
    const float4* g     = (const float4*)d_in[1];
    const int*    f_len = (const int*)d_in[2];
    const int*    g_len = (const int*)d_in[3];
    float4*       out   = (float4*)d_out;

    dim3 grid(T_, B_);      // (256, 16) = 4096 CTAs, one per (b,t) row
    dim3 block(256);
    transducer_joint_kernel<<<grid, block>>>(f, g, f_len, g_len, out);
}

// round 7
// speedup vs baseline: 1.0685x; 1.0685x over previous
#include <cuda_runtime.h>

// TransducerJoint: h[b,t,u,:] = f[b,t,:] + g[b,u,:] if t < f_len[b] && u < g_len[b] else 0
// B=16, T=256, U=96, H=512 (fp32). Output 805 MB -> pure HBM-write-bound.
// R7: champion R2 structure (U_PER_BLK=8, 16KB span/CTA, fully-unrolled
//     predicated body, float4 __stcs) + hoisted scalar n_valid predicate (R5).

#define B_ 16
#define T_ 256
#define U_ 96
#define H_ 512
#define H4_ (H_ / 4)      // 128 float4 per H-row
#define U_PER_BLK 8

__global__ __launch_bounds__(H4_) void transducer_joint_kernel(
    const float4* __restrict__ f,      // (B, T, H/4)
    const float4* __restrict__ g,      // (B, U, H/4)
    const int*    __restrict__ f_len,  // (B,)
    const int*    __restrict__ g_len,  // (B,)
    float4*       __restrict__ out)    // (B, T, U, H/4)
{
    const int h4 = threadIdx.x;        // 0..127
    const int u0 = blockIdx.x * U_PER_BLK;
    const int t  = blockIdx.y;
    const int b  = blockIdx.z;

    // valid u count within [u0, u0+U_PER_BLK), computed once
    int n_valid = 0;
    if (t < f_len[b]) {
        int r = g_len[b] - u0;
        n_valid = r < 0 ? 0 : (r > U_PER_BLK ? U_PER_BLK : r);
    }

    // f row chunk: loaded once, reused for all 8 u's
    const float4 f4 = __ldg(f + ((size_t)b * T_ + t) * H4_ + h4);

    const float4* gbase = g + ((size_t)b * U_ + u0) * H4_ + h4;
    float4* obase = out + (((size_t)b * T_ + t) * U_ + u0) * H4_ + h4;

    const float4 zero = make_float4(0.f, 0.f, 0.f, 0.f);

#pragma unroll
    for (int du = 0; du < U_PER_BLK; ++du) {
        float4 r = zero;
        if (du < n_valid) {                       // single scalar predicate
            const float4 g4 = __ldg(gbase + (size_t)du * H4_);
            r.x = f4.x + g4.x;
            r.y = f4.y + g4.y;
            r.z = f4.z + g4.z;
            r.w = f4.w + g4.w;
        }
        __stcs(obase + (size_t)du * H4_, r);      // unconditional streaming store
    }
}

extern "C" void kernel_launch(void* const* d_in, const int* in_sizes, int n_in,
                              void* d_out, int out_size)
{
    const float4* f     = (const float4*)d_in[0];
    const float4* g     = (const float4*)d_in[1];
    const int*    f_len = (const int*)d_in[2];
    const int*    g_len = (const int*)d_in[3];
    float4*       out   = (float4*)d_out;

    dim3 grid(U_ / U_PER_BLK, T_, B_);   // (12, 256, 16) = 49152 CTAs
    dim3 block(H4_);                      // 128 threads
    transducer_joint_kernel<<<grid, block>>>(f, g, f_len, g_len, out);
}

// round 8
// speedup vs baseline: 1.0842x; 1.0147x over previous
#include <cuda_runtime.h>

// TransducerJoint: h[b,t,u,:] = f[b,t,:] + g[b,u,:] if t < f_len[b] && u < g_len[b] else 0
// B=16, T=256, U=96, H=512 (fp32). Output 805 MB -> pure HBM-write-bound.
// R8: span-size sweep endpoint: U_PER_BLK=4 (8KB span, 98304 CTAs) with the
//     proven body (float4 __stcs, hoisted n_valid, full unroll) and
//     launch_bounds-forced 32 regs for max occupancy / concurrent writers.

#define B_ 16
#define T_ 256
#define U_ 96
#define H_ 512
#define H4_ (H_ / 4)      // 128 float4 per H-row
#define U_PER_BLK 4

__global__ __launch_bounds__(H4_, 16) void transducer_joint_kernel(
    const float4* __restrict__ f,      // (B, T, H/4)
    const float4* __restrict__ g,      // (B, U, H/4)
    const int*    __restrict__ f_len,  // (B,)
    const int*    __restrict__ g_len,  // (B,)
    float4*       __restrict__ out)    // (B, T, U, H/4)
{
    const int h4 = threadIdx.x;        // 0..127
    const int u0 = blockIdx.x * U_PER_BLK;
    const int t  = blockIdx.y;
    const int b  = blockIdx.z;

    // valid u count within [u0, u0+U_PER_BLK), computed once
    int n_valid = 0;
    if (t < f_len[b]) {
        int r = g_len[b] - u0;
        n_valid = r < 0 ? 0 : (r > U_PER_BLK ? U_PER_BLK : r);
    }

    // f row chunk: loaded once, reused for all 4 u's
    const float4 f4 = __ldg(f + ((size_t)b * T_ + t) * H4_ + h4);

    const float4* gbase = g + ((size_t)b * U_ + u0) * H4_ + h4;
    float4* obase = out + (((size_t)b * T_ + t) * U_ + u0) * H4_ + h4;

    const float4 zero = make_float4(0.f, 0.f, 0.f, 0.f);

#pragma unroll
    for (int du = 0; du < U_PER_BLK; ++du) {
        float4 r = zero;
        if (du < n_valid) {                       // single scalar predicate
            const float4 g4 = __ldg(gbase + (size_t)du * H4_);
            r.x = f4.x + g4.x;
            r.y = f4.y + g4.y;
            r.z = f4.z + g4.z;
            r.w = f4.w + g4.w;
        }
        __stcs(obase + (size_t)du * H4_, r);      // unconditional streaming store
    }
}

extern "C" void kernel_launch(void* const* d_in, const int* in_sizes, int n_in,
                              void* d_out, int out_size)
{
    const float4* f     = (const float4*)d_in[0];
    const float4* g     = (const float4*)d_in[1];
    const int*    f_len = (const int*)d_in[2];
    const int*    g_len = (const int*)d_in[3];
    float4*       out   = (float4*)d_out;

    dim3 grid(U_ / U_PER_BLK, T_, B_);   // (24, 256, 16) = 98304 CTAs
    dim3 block(H4_);                      // 128 threads
    transducer_joint_kernel<<<grid, block>>>(f, g, f_len, g_len, out);
}